// round 12
// baseline (speedup 1.0000x reference)
#include <cuda_runtime.h>
#include <cuda_bf16.h>
#include <math.h>
#include <stdint.h>

// ContrastiveLoss via warp-level bf16 mma.sync (HMMA), 2 launches.
// loss = log(S_A_up + S_C_up + S_B_full + sim_s) - log(sim_s)
//   A=UU^T, C=VV^T, B=UV^T on L2-normalized halves.
//   sim_s = sum exp(diag(B)/2), harvested from the 32 diagonal B tiles.
// Final log folded into tile_k's last CTA (fp32 only).
//
// g_xb layout (fragment-order, removes all swizzle math from the mainloop):
//   64 bands of 128 rows; band = 4 K-blocks (64 k each, 16KB contiguous).
//   K-block = 16 row-groups (g8=row>>3) x 8 column-halves (h=kbyte>>4) of
//   128B ldmatrix atoms at (g8*8+h)*128; within an atom, row slot =
//   (row&7)^h (keeps normalize stores bank-conflict-free).
//   -> LDSM address = fragBase + sks[ks], one IADD.

#define D      256
#define NROWS  8192
#define NT     32
#define NTILES 2080
#define BAND_BYTES 65536
#define KBLK_BYTES 16384
#define STAGE_BYTES 32768              // A 16KB + B 16KB
#define SMEM_DATA   1024
#define SMEM_TOTAL  (SMEM_DATA + 2 * STAGE_BYTES)   // 66560

#define MB_FULL0  16
#define MB_FULL1  24
#define MB_EMPTY0 32
#define MB_EMPTY1 40

__device__ __align__(128) uint8_t g_xb[NROWS * D * 2];   // 4 MB bf16
__device__ double g_main;
__device__ double g_sims;
__device__ int    g_done;

// ---------------------------------------------------------------------------
static __device__ __forceinline__ uint32_t smem_u32(const void* p) {
    uint32_t a;
    asm("{ .reg .u64 t; cvta.to.shared.u64 t, %1; cvt.u32.u64 %0, t; }"
        : "=r"(a) : "l"(p));
    return a;
}

static __device__ __forceinline__ float ex2f(float x) {
    float y;
    asm("ex2.approx.f32 %0, %1;" : "=f"(y) : "f"(x));
    return y;
}
#define EXP_HALF_LOG2E 0.7213475204444817f   // 0.5 * log2(e)

static __device__ __forceinline__ float lg2f(float x) {
    float y;
    asm("lg2.approx.f32 %0, %1;" : "=f"(y) : "f"(x));
    return y;
}
#define LN2F 0.6931471805599453f

#define MBAR_INIT(addr, cnt) \
    asm volatile("mbarrier.init.shared.b64 [%0], %1;" :: "r"(addr), "r"(cnt) : "memory")

#define MBAR_ARRIVE(addr) \
    asm volatile("mbarrier.arrive.shared.b64 _, [%0];" :: "r"(addr) : "memory")

#define MBAR_EXPECT_TX(addr, bytes) \
    asm volatile("mbarrier.arrive.expect_tx.shared.b64 _, [%0], %1;" \
                 :: "r"(addr), "r"(bytes) : "memory")

#define MBAR_WAIT(addr, parity) do {                                          \
    uint32_t _m = (addr); uint32_t _p = (parity); uint32_t _done;             \
    asm volatile("{\n\t.reg .pred p;\n\t"                                     \
        "mbarrier.try_wait.parity.acquire.cta.shared::cta.b64 p, [%1], %2;\n\t"\
        "selp.b32 %0, 1, 0, p;\n\t}"                                          \
        : "=r"(_done) : "r"(_m), "r"(_p) : "memory");                         \
    if (!_done) {                                                             \
        asm volatile("{\n\t.reg .pred P1;\n\t"                                \
            "W_%=:\n\t"                                                       \
            "mbarrier.try_wait.parity.acquire.cta.shared::cta.b64 P1, [%0], %1, 0x989680;\n\t" \
            "@P1 bra.uni WD_%=;\n\t"                                          \
            "bra.uni W_%=;\n\t"                                               \
            "WD_%=:\n\t}" :: "r"(_m), "r"(_p) : "memory");                    \
    }                                                                         \
} while (0)

#define BULK_G2S(dst, src, bytes, mbar) \
    asm volatile("cp.async.bulk.shared::cta.global.mbarrier::complete_tx::bytes [%0], [%1], %2, [%3];" \
                 :: "r"(dst), "l"(src), "r"(bytes), "r"(mbar) : "memory")

static __device__ __forceinline__ void ldsm_x4(uint32_t* r, uint32_t addr) {
    asm volatile("ldmatrix.sync.aligned.m8n8.x4.shared.b16 {%0,%1,%2,%3}, [%4];"
                 : "=r"(r[0]), "=r"(r[1]), "=r"(r[2]), "=r"(r[3]) : "r"(addr));
}

static __device__ __forceinline__ void mma16816(float* d, const uint32_t* a,
                                                uint32_t b0, uint32_t b1) {
    asm volatile("mma.sync.aligned.m16n8k16.row.col.f32.bf16.bf16.f32 "
                 "{%0,%1,%2,%3}, {%4,%5,%6,%7}, {%8,%9}, {%0,%1,%2,%3};"
                 : "+f"(d[0]), "+f"(d[1]), "+f"(d[2]), "+f"(d[3])
                 : "r"(a[0]), "r"(a[1]), "r"(a[2]), "r"(a[3]), "r"(b0), "r"(b1));
}

// ---------------------------------------------------------------------------
// Two rows per warp. Block 0 zeroes accumulators (stream-ordered).
__global__ __launch_bounds__(256) void normalize_k(const float* __restrict__ x) {
    const int tid  = threadIdx.x;
    const int wid  = tid >> 5;
    const int lane = tid & 31;
    const int r0   = blockIdx.x * 16 + wid * 2;
    const int r1   = r0 + 1;
    if (blockIdx.x == 0 && tid == 0) { g_main = 0.0; g_sims = 0.0; }

    const float4* x0 = (const float4*)(x + r0 * D);
    const float4* x1 = (const float4*)(x + r1 * D);
    float4 a0 = x0[lane * 2 + 0];
    float4 a1 = x0[lane * 2 + 1];
    float4 b0 = x1[lane * 2 + 0];
    float4 b1 = x1[lane * 2 + 1];

    float sa = a0.x * a0.x + a0.y * a0.y + a0.z * a0.z + a0.w * a0.w
             + a1.x * a1.x + a1.y * a1.y + a1.z * a1.z + a1.w * a1.w;
    float sb = b0.x * b0.x + b0.y * b0.y + b0.z * b0.z + b0.w * b0.w
             + b1.x * b1.x + b1.y * b1.y + b1.z * b1.z + b1.w * b1.w;
    #pragma unroll
    for (int o = 16; o > 0; o >>= 1) {
        sa += __shfl_xor_sync(0xFFFFFFFFu, sa, o);
        sb += __shfl_xor_sync(0xFFFFFFFFu, sb, o);
    }
    float ia = 1.0f / fmaxf(sqrtf(sa), 1e-8f);
    float ib = 1.0f / fmaxf(sqrtf(sb), 1e-8f);

    uint32_t pa[4], pb[4];
    pa[0] = (uint32_t)__bfloat16_as_ushort(__float2bfloat16(a0.x * ia))
          | ((uint32_t)__bfloat16_as_ushort(__float2bfloat16(a0.y * ia)) << 16);
    pa[1] = (uint32_t)__bfloat16_as_ushort(__float2bfloat16(a0.z * ia))
          | ((uint32_t)__bfloat16_as_ushort(__float2bfloat16(a0.w * ia)) << 16);
    pa[2] = (uint32_t)__bfloat16_as_ushort(__float2bfloat16(a1.x * ia))
          | ((uint32_t)__bfloat16_as_ushort(__float2bfloat16(a1.y * ia)) << 16);
    pa[3] = (uint32_t)__bfloat16_as_ushort(__float2bfloat16(a1.z * ia))
          | ((uint32_t)__bfloat16_as_ushort(__float2bfloat16(a1.w * ia)) << 16);
    pb[0] = (uint32_t)__bfloat16_as_ushort(__float2bfloat16(b0.x * ib))
          | ((uint32_t)__bfloat16_as_ushort(__float2bfloat16(b0.y * ib)) << 16);
    pb[1] = (uint32_t)__bfloat16_as_ushort(__float2bfloat16(b0.z * ib))
          | ((uint32_t)__bfloat16_as_ushort(__float2bfloat16(b0.w * ib)) << 16);
    pb[2] = (uint32_t)__bfloat16_as_ushort(__float2bfloat16(b1.x * ib))
          | ((uint32_t)__bfloat16_as_ushort(__float2bfloat16(b1.y * ib)) << 16);
    pb[3] = (uint32_t)__bfloat16_as_ushort(__float2bfloat16(b1.z * ib))
          | ((uint32_t)__bfloat16_as_ushort(__float2bfloat16(b1.w * ib)) << 16);

    // lane covers k = lane*8..+7 -> 16B at column-half h = lane&7 of
    // K-block kb = lane>>3. Atom (g8*8+h)*128, row slot (rib&7)^h.
    const int band = r0 >> 7;
    const int kb   = lane >> 3;
    const int h    = lane & 7;
    uint8_t* bandp = g_xb + (size_t)band * BAND_BYTES + (size_t)kb * KBLK_BYTES;
    const int rib0 = r0 & 127, rib1 = rib0 + 1;
    uint32_t o0 = (uint32_t)((rib0 >> 3) * 1024 + h * 128 + ((rib0 & 7) ^ h) * 16);
    uint32_t o1 = (uint32_t)((rib1 >> 3) * 1024 + h * 128 + ((rib1 & 7) ^ h) * 16);
    *(uint4*)(bandp + o0) = *(uint4*)pa;
    *(uint4*)(bandp + o1) = *(uint4*)pb;
}

// ---------------------------------------------------------------------------
// One CTA = one 128x128x256 tile. Fragment semantics identical to the
// verified R5 kernel; only LDSM addressing changed (1 IADD per load).
__global__ __launch_bounds__(256, 2) void tile_k(float* __restrict__ out) {
    extern __shared__ __align__(1024) uint8_t smem[];
    uint32_t sb = smem_u32(smem);
    const int tid  = threadIdx.x;
    const int wid  = tid >> 5;
    const int lane = tid & 31;

    // ---- tile decode ----
    int t = blockIdx.x;
    int bi, bj;
    bool maskt = false, bdiag = false;
    const uint8_t *gA, *gB;
    if (t < 1024) {                       // B = U V^T, full
        bi = t >> 5; bj = t & 31;
        bdiag = (bi == bj);               // carries diag(B) -> sim_s
        gA = g_xb + (size_t)bi * BAND_BYTES;
        gB = g_xb + (size_t)(32 + bj) * BAND_BYTES;
    } else {                              // A (m=0) / C (m=1), upper
        t -= 1024;
        int m = (t >= 528) ? 1 : 0;
        int u = t - m * 528;
        int b_ = 0;
        while (u >= NT - b_) { u -= NT - b_; b_++; }
        bi = b_; bj = b_ + u;
        maskt = (bi == bj);
        gA = g_xb + (size_t)(m * 32 + bi) * BAND_BYTES;
        gB = g_xb + (size_t)(m * 32 + bj) * BAND_BYTES;
    }

    if (tid == 0) {
        MBAR_INIT(sb + MB_FULL0, 1);  MBAR_INIT(sb + MB_FULL1, 1);
        MBAR_INIT(sb + MB_EMPTY0, 8); MBAR_INIT(sb + MB_EMPTY1, 8);
    }
    __syncthreads();

    if (tid == 0) {
        #pragma unroll
        for (int s = 0; s < 2; s++) {
            uint32_t stb = sb + SMEM_DATA + s * STAGE_BYTES;
            uint32_t fb  = sb + MB_FULL0 + 8 * s;
            MBAR_EXPECT_TX(fb, (uint32_t)STAGE_BYTES);
            BULK_G2S(stb,         gA + s * KBLK_BYTES, KBLK_BYTES, fb);
            BULK_G2S(stb + 16384, gB + s * KBLK_BYTES, KBLK_BYTES, fb);
        }
    }

    // ---- fragment-order addressing: per-lane constants ----
    const int warp_m = wid & 3;          // 32-row strip
    const int warp_n = wid >> 2;         // 64-col strip
    const int l7   = lane & 7;
    const int lsel = (lane >> 3) & 1;    // second 8-row group
    const int hb   = lane >> 4;          // second 16B column half

    uint32_t sks[4];
    #pragma unroll
    for (int ks = 0; ks < 4; ks++) {
        int h = 2 * ks + hb;
        sks[ks] = (uint32_t)(h * 128 + ((l7 ^ h) * 16));
    }
    uint32_t aOff[2], bOff[4];
    aOff[0] = (uint32_t)((warp_m * 4 + lsel) * 1024);
    aOff[1] = aOff[0] + 2048;
    #pragma unroll
    for (int bg = 0; bg < 4; bg++)
        bOff[bg] = (uint32_t)((warp_n * 8 + bg * 2 + lsel) * 1024);

    float d[2][8][4];
    #pragma unroll
    for (int i = 0; i < 2; i++)
        #pragma unroll
        for (int j = 0; j < 8; j++)
            #pragma unroll
            for (int k = 0; k < 4; k++) d[i][j][k] = 0.0f;

    // ---- chunk loop: 4 chunks of K=64, double-buffered ----
    #pragma unroll
    for (int c = 0; c < 4; c++) {
        const int st = c & 1;
        const uint32_t stA = sb + SMEM_DATA + st * STAGE_BYTES;
        const uint32_t stB = stA + 16384;
        MBAR_WAIT(sb + MB_FULL0 + 8 * st, (uint32_t)((c >> 1) & 1));

        #pragma unroll
        for (int ks = 0; ks < 4; ks++) {
            uint32_t a[2][4], b[4][4];
            #pragma unroll
            for (int am = 0; am < 2; am++)
                ldsm_x4(a[am], stA + aOff[am] + sks[ks]);
            #pragma unroll
            for (int bg = 0; bg < 4; bg++)
                ldsm_x4(b[bg], stB + bOff[bg] + sks[ks]);

            #pragma unroll
            for (int am = 0; am < 2; am++)
                #pragma unroll
                for (int bg = 0; bg < 4; bg++) {
                    mma16816(d[am][bg * 2 + 0], a[am], b[bg][0], b[bg][2]);
                    mma16816(d[am][bg * 2 + 1], a[am], b[bg][1], b[bg][3]);
                }
        }

        if (lane == 0) MBAR_ARRIVE(sb + MB_EMPTY0 + 8 * st);
        if (tid == 0 && c < 2) {
            MBAR_WAIT(sb + MB_EMPTY0 + 8 * st, 0u);
            uint32_t fb = sb + MB_FULL0 + 8 * st;
            MBAR_EXPECT_TX(fb, (uint32_t)STAGE_BYTES);
            BULK_G2S(stA, gA + (c + 2) * KBLK_BYTES, KBLK_BYTES, fb);
            BULK_G2S(stB, gB + (c + 2) * KBLK_BYTES, KBLK_BYTES, fb);
        }
    }

    // ---- epilogue: exp2(d * 0.5*log2 e) -> reduce; uniform tile-type branch ----
    const int rbase = warp_m * 32 + (lane >> 2);
    const int cbase = warp_n * 64 + 2 * (lane & 3);
    float sum = 0.0f;
    float sumd = 0.0f;

    if (!maskt && !bdiag) {
        #pragma unroll
        for (int am = 0; am < 2; am++)
            #pragma unroll
            for (int bn = 0; bn < 8; bn++)
                #pragma unroll
                for (int k = 0; k < 4; k++)
                    sum += ex2f(d[am][bn][k] * EXP_HALF_LOG2E);
    } else if (maskt) {
        #pragma unroll
        for (int am = 0; am < 2; am++)
            #pragma unroll
            for (int bn = 0; bn < 8; bn++)
                #pragma unroll
                for (int k = 0; k < 4; k++) {
                    float e = ex2f(d[am][bn][k] * EXP_HALF_LOG2E);
                    int row = rbase + am * 16 + ((k >> 1) << 3);
                    int col = cbase + bn * 8 + (k & 1);
                    sum += (col >= row) ? e : 0.0f;
                }
    } else {  // bdiag: full sum + harvest diagonal into sim_s
        #pragma unroll
        for (int am = 0; am < 2; am++)
            #pragma unroll
            for (int bn = 0; bn < 8; bn++)
                #pragma unroll
                for (int k = 0; k < 4; k++) {
                    float e = ex2f(d[am][bn][k] * EXP_HALF_LOG2E);
                    int row = rbase + am * 16 + ((k >> 1) << 3);
                    int col = cbase + bn * 8 + (k & 1);
                    sum += e;
                    if (row == col) sumd += e;
                }
    }

    #pragma unroll
    for (int o = 16; o > 0; o >>= 1)
        sum += __shfl_xor_sync(0xFFFFFFFFu, sum, o);

    __shared__ float wsum[8];
    if (lane == 0) wsum[wid] = sum;

    if (bdiag) {
        #pragma unroll
        for (int o = 16; o > 0; o >>= 1)
            sumd += __shfl_xor_sync(0xFFFFFFFFu, sumd, o);
        __shared__ float wsumd[8];
        if (lane == 0) wsumd[wid] = sumd;
        __syncthreads();
        if (tid == 0) {
            float s = 0.0f, sd = 0.0f;
            #pragma unroll
            for (int i = 0; i < 8; i++) { s += wsum[i]; sd += wsumd[i]; }
            atomicAdd(&g_main, (double)s);
            atomicAdd(&g_sims, (double)sd);
        }
    } else {
        __syncthreads();
        if (tid == 0) {
            float s = 0.0f;
            #pragma unroll
            for (int i = 0; i < 8; i++) s += wsum[i];
            atomicAdd(&g_main, (double)s);
        }
    }

    // ---- finalizer: last CTA computes the loss (fp32 only; cold branch) ----
    if (tid == 0) {
        __threadfence();
        int prev = atomicAdd(&g_done, 1);
        if (prev == NTILES - 1) {
            float mn   = (float)atomicAdd(&g_main, 0.0);   // coherent read
            float sims = (float)atomicAdd(&g_sims, 0.0);
            out[0] = lg2f((mn + sims) / sims) * LN2F;
            g_done = 0;                                    // replay-safe reset
            __threadfence();
        }
    }
}

// ---------------------------------------------------------------------------
extern "C" void kernel_launch(void* const* d_in, const int* in_sizes, int n_in,
                              void* d_out, int out_size) {
    const float* x = (const float*)d_in[0];
    float* out = (float*)d_out;

    cudaFuncSetAttribute(tile_k, cudaFuncAttributeMaxDynamicSharedMemorySize, SMEM_TOTAL);

    normalize_k<<<NROWS / 16, 256>>>(x);
    tile_k<<<NTILES, 256, SMEM_TOTAL>>>(out);
}

// round 13
// speedup vs baseline: 1.0006x; 1.0006x over previous
#include <cuda_runtime.h>
#include <cuda_bf16.h>
#include <math.h>
#include <stdint.h>

// ContrastiveLoss via warp-level bf16 mma.sync (HMMA), 2 launches.
// loss = log(S_A_up + S_C_up + S_B_full + sim_s) - log(sim_s)
//   A=UU^T, C=VV^T, B=UV^T on L2-normalized halves.
//   sim_s = sum exp(diag(B)/2), harvested from the 32 diagonal B tiles.
// Final log folded into tile_k's last CTA (fp32 only).
//
// 3-stage pipeline: chunks 0,1,2 prefetched at CTA start; single refill
// (chunk 3 -> stage 0) hides under two chunks of compute. All stage
// indices compile-time constant.
//
// g_xb layout (fragment-order): 64 bands of 128 rows; band = 4 K-blocks
// (64 k each, 16KB). K-block = ldmatrix atoms (g8*8+h)*128, row slot
// (row&7)^h. LDSM address = fragBase + sks[ks].

#define D      256
#define NROWS  8192
#define NT     32
#define NTILES 2080
#define BAND_BYTES 65536
#define KBLK_BYTES 16384
#define STAGE_BYTES 32768              // A 16KB + B 16KB
#define SMEM_DATA   1024
#define SMEM_TOTAL  (SMEM_DATA + 3 * STAGE_BYTES)   // 99328

#define MB_FULL0  16
#define MB_FULL1  24
#define MB_FULL2  32
#define MB_EMPTY0 40

__device__ __align__(128) uint8_t g_xb[NROWS * D * 2];   // 4 MB bf16
__device__ double g_main;
__device__ double g_sims;
__device__ int    g_done;

// ---------------------------------------------------------------------------
static __device__ __forceinline__ uint32_t smem_u32(const void* p) {
    uint32_t a;
    asm("{ .reg .u64 t; cvta.to.shared.u64 t, %1; cvt.u32.u64 %0, t; }"
        : "=r"(a) : "l"(p));
    return a;
}

static __device__ __forceinline__ float ex2f(float x) {
    float y;
    asm("ex2.approx.f32 %0, %1;" : "=f"(y) : "f"(x));
    return y;
}
#define EXP_HALF_LOG2E 0.7213475204444817f   // 0.5 * log2(e)

static __device__ __forceinline__ float lg2f(float x) {
    float y;
    asm("lg2.approx.f32 %0, %1;" : "=f"(y) : "f"(x));
    return y;
}
#define LN2F 0.6931471805599453f

#define MBAR_INIT(addr, cnt) \
    asm volatile("mbarrier.init.shared.b64 [%0], %1;" :: "r"(addr), "r"(cnt) : "memory")

#define MBAR_ARRIVE(addr) \
    asm volatile("mbarrier.arrive.shared.b64 _, [%0];" :: "r"(addr) : "memory")

#define MBAR_EXPECT_TX(addr, bytes) \
    asm volatile("mbarrier.arrive.expect_tx.shared.b64 _, [%0], %1;" \
                 :: "r"(addr), "r"(bytes) : "memory")

#define MBAR_WAIT(addr, parity) do {                                          \
    uint32_t _m = (addr); uint32_t _p = (parity); uint32_t _done;             \
    asm volatile("{\n\t.reg .pred p;\n\t"                                     \
        "mbarrier.try_wait.parity.acquire.cta.shared::cta.b64 p, [%1], %2;\n\t"\
        "selp.b32 %0, 1, 0, p;\n\t}"                                          \
        : "=r"(_done) : "r"(_m), "r"(_p) : "memory");                         \
    if (!_done) {                                                             \
        asm volatile("{\n\t.reg .pred P1;\n\t"                                \
            "W_%=:\n\t"                                                       \
            "mbarrier.try_wait.parity.acquire.cta.shared::cta.b64 P1, [%0], %1, 0x989680;\n\t" \
            "@P1 bra.uni WD_%=;\n\t"                                          \
            "bra.uni W_%=;\n\t"                                               \
            "WD_%=:\n\t}" :: "r"(_m), "r"(_p) : "memory");                    \
    }                                                                         \
} while (0)

#define BULK_G2S(dst, src, bytes, mbar) \
    asm volatile("cp.async.bulk.shared::cta.global.mbarrier::complete_tx::bytes [%0], [%1], %2, [%3];" \
                 :: "r"(dst), "l"(src), "r"(bytes), "r"(mbar) : "memory")

static __device__ __forceinline__ void ldsm_x4(uint32_t* r, uint32_t addr) {
    asm volatile("ldmatrix.sync.aligned.m8n8.x4.shared.b16 {%0,%1,%2,%3}, [%4];"
                 : "=r"(r[0]), "=r"(r[1]), "=r"(r[2]), "=r"(r[3]) : "r"(addr));
}

static __device__ __forceinline__ void mma16816(float* d, const uint32_t* a,
                                                uint32_t b0, uint32_t b1) {
    asm volatile("mma.sync.aligned.m16n8k16.row.col.f32.bf16.bf16.f32 "
                 "{%0,%1,%2,%3}, {%4,%5,%6,%7}, {%8,%9}, {%0,%1,%2,%3};"
                 : "+f"(d[0]), "+f"(d[1]), "+f"(d[2]), "+f"(d[3])
                 : "r"(a[0]), "r"(a[1]), "r"(a[2]), "r"(a[3]), "r"(b0), "r"(b1));
}

// ---------------------------------------------------------------------------
// Two rows per warp. Block 0 zeroes accumulators (stream-ordered).
__global__ __launch_bounds__(256) void normalize_k(const float* __restrict__ x) {
    const int tid  = threadIdx.x;
    const int wid  = tid >> 5;
    const int lane = tid & 31;
    const int r0   = blockIdx.x * 16 + wid * 2;
    const int r1   = r0 + 1;
    if (blockIdx.x == 0 && tid == 0) { g_main = 0.0; g_sims = 0.0; }

    const float4* x0 = (const float4*)(x + r0 * D);
    const float4* x1 = (const float4*)(x + r1 * D);
    float4 a0 = x0[lane * 2 + 0];
    float4 a1 = x0[lane * 2 + 1];
    float4 b0 = x1[lane * 2 + 0];
    float4 b1 = x1[lane * 2 + 1];

    float sa = a0.x * a0.x + a0.y * a0.y + a0.z * a0.z + a0.w * a0.w
             + a1.x * a1.x + a1.y * a1.y + a1.z * a1.z + a1.w * a1.w;
    float sb = b0.x * b0.x + b0.y * b0.y + b0.z * b0.z + b0.w * b0.w
             + b1.x * b1.x + b1.y * b1.y + b1.z * b1.z + b1.w * b1.w;
    #pragma unroll
    for (int o = 16; o > 0; o >>= 1) {
        sa += __shfl_xor_sync(0xFFFFFFFFu, sa, o);
        sb += __shfl_xor_sync(0xFFFFFFFFu, sb, o);
    }
    float ia = 1.0f / fmaxf(sqrtf(sa), 1e-8f);
    float ib = 1.0f / fmaxf(sqrtf(sb), 1e-8f);

    uint32_t pa[4], pb[4];
    pa[0] = (uint32_t)__bfloat16_as_ushort(__float2bfloat16(a0.x * ia))
          | ((uint32_t)__bfloat16_as_ushort(__float2bfloat16(a0.y * ia)) << 16);
    pa[1] = (uint32_t)__bfloat16_as_ushort(__float2bfloat16(a0.z * ia))
          | ((uint32_t)__bfloat16_as_ushort(__float2bfloat16(a0.w * ia)) << 16);
    pa[2] = (uint32_t)__bfloat16_as_ushort(__float2bfloat16(a1.x * ia))
          | ((uint32_t)__bfloat16_as_ushort(__float2bfloat16(a1.y * ia)) << 16);
    pa[3] = (uint32_t)__bfloat16_as_ushort(__float2bfloat16(a1.z * ia))
          | ((uint32_t)__bfloat16_as_ushort(__float2bfloat16(a1.w * ia)) << 16);
    pb[0] = (uint32_t)__bfloat16_as_ushort(__float2bfloat16(b0.x * ib))
          | ((uint32_t)__bfloat16_as_ushort(__float2bfloat16(b0.y * ib)) << 16);
    pb[1] = (uint32_t)__bfloat16_as_ushort(__float2bfloat16(b0.z * ib))
          | ((uint32_t)__bfloat16_as_ushort(__float2bfloat16(b0.w * ib)) << 16);
    pb[2] = (uint32_t)__bfloat16_as_ushort(__float2bfloat16(b1.x * ib))
          | ((uint32_t)__bfloat16_as_ushort(__float2bfloat16(b1.y * ib)) << 16);
    pb[3] = (uint32_t)__bfloat16_as_ushort(__float2bfloat16(b1.z * ib))
          | ((uint32_t)__bfloat16_as_ushort(__float2bfloat16(b1.w * ib)) << 16);

    const int band = r0 >> 7;
    const int kb   = lane >> 3;
    const int h    = lane & 7;
    uint8_t* bandp = g_xb + (size_t)band * BAND_BYTES + (size_t)kb * KBLK_BYTES;
    const int rib0 = r0 & 127, rib1 = rib0 + 1;
    uint32_t o0 = (uint32_t)((rib0 >> 3) * 1024 + h * 128 + ((rib0 & 7) ^ h) * 16);
    uint32_t o1 = (uint32_t)((rib1 >> 3) * 1024 + h * 128 + ((rib1 & 7) ^ h) * 16);
    *(uint4*)(bandp + o0) = *(uint4*)pa;
    *(uint4*)(bandp + o1) = *(uint4*)pb;
}

// ---------------------------------------------------------------------------
// One CTA = one 128x128x256 tile. 3-stage pipeline, single refill.
__global__ __launch_bounds__(256, 2) void tile_k(float* __restrict__ out) {
    extern __shared__ __align__(1024) uint8_t smem[];
    uint32_t sb = smem_u32(smem);
    const int tid  = threadIdx.x;
    const int wid  = tid >> 5;
    const int lane = tid & 31;

    // ---- tile decode ----
    int t = blockIdx.x;
    int bi, bj;
    bool maskt = false, bdiag = false;
    const uint8_t *gA, *gB;
    if (t < 1024) {                       // B = U V^T, full
        bi = t >> 5; bj = t & 31;
        bdiag = (bi == bj);               // carries diag(B) -> sim_s
        gA = g_xb + (size_t)bi * BAND_BYTES;
        gB = g_xb + (size_t)(32 + bj) * BAND_BYTES;
    } else {                              // A (m=0) / C (m=1), upper
        t -= 1024;
        int m = (t >= 528) ? 1 : 0;
        int u = t - m * 528;
        int b_ = 0;
        while (u >= NT - b_) { u -= NT - b_; b_++; }
        bi = b_; bj = b_ + u;
        maskt = (bi == bj);
        gA = g_xb + (size_t)(m * 32 + bi) * BAND_BYTES;
        gB = g_xb + (size_t)(m * 32 + bj) * BAND_BYTES;
    }

    if (tid == 0) {
        MBAR_INIT(sb + MB_FULL0, 1);  MBAR_INIT(sb + MB_FULL1, 1);
        MBAR_INIT(sb + MB_FULL2, 1);  MBAR_INIT(sb + MB_EMPTY0, 8);
    }
    __syncthreads();

    // Prologue: chunks 0,1,2 into stages 0,1,2.
    if (tid == 0) {
        #pragma unroll
        for (int s = 0; s < 3; s++) {
            uint32_t stb = sb + SMEM_DATA + s * STAGE_BYTES;
            uint32_t fb  = sb + MB_FULL0 + 8 * s;
            MBAR_EXPECT_TX(fb, (uint32_t)STAGE_BYTES);
            BULK_G2S(stb,         gA + s * KBLK_BYTES, KBLK_BYTES, fb);
            BULK_G2S(stb + 16384, gB + s * KBLK_BYTES, KBLK_BYTES, fb);
        }
    }

    // ---- fragment-order addressing: per-lane constants ----
    const int warp_m = wid & 3;          // 32-row strip
    const int warp_n = wid >> 2;         // 64-col strip
    const int l7   = lane & 7;
    const int lsel = (lane >> 3) & 1;
    const int hb   = lane >> 4;

    uint32_t sks[4];
    #pragma unroll
    for (int ks = 0; ks < 4; ks++) {
        int h = 2 * ks + hb;
        sks[ks] = (uint32_t)(h * 128 + ((l7 ^ h) * 16));
    }
    uint32_t aOff[2], bOff[4];
    aOff[0] = (uint32_t)((warp_m * 4 + lsel) * 1024);
    aOff[1] = aOff[0] + 2048;
    #pragma unroll
    for (int bg = 0; bg < 4; bg++)
        bOff[bg] = (uint32_t)((warp_n * 8 + bg * 2 + lsel) * 1024);

    float d[2][8][4];
    #pragma unroll
    for (int i = 0; i < 2; i++)
        #pragma unroll
        for (int j = 0; j < 8; j++)
            #pragma unroll
            for (int k = 0; k < 4; k++) d[i][j][k] = 0.0f;

    // ---- chunk loop: c0->s0, c1->s1, c2->s2, c3->s0 (parity 1) ----
    #pragma unroll
    for (int c = 0; c < 4; c++) {
        const int st = (c < 3) ? c : 0;
        const uint32_t stA = sb + SMEM_DATA + st * STAGE_BYTES;
        const uint32_t stB = stA + 16384;
        MBAR_WAIT(sb + MB_FULL0 + 8 * st, (uint32_t)((c == 3) ? 1 : 0));

        #pragma unroll
        for (int ks = 0; ks < 4; ks++) {
            uint32_t a[2][4], b[4][4];
            #pragma unroll
            for (int am = 0; am < 2; am++)
                ldsm_x4(a[am], stA + aOff[am] + sks[ks]);
            #pragma unroll
            for (int bg = 0; bg < 4; bg++)
                ldsm_x4(b[bg], stB + bOff[bg] + sks[ks]);

            #pragma unroll
            for (int am = 0; am < 2; am++)
                #pragma unroll
                for (int bg = 0; bg < 4; bg++) {
                    mma16816(d[am][bg * 2 + 0], a[am], b[bg][0], b[bg][2]);
                    mma16816(d[am][bg * 2 + 1], a[am], b[bg][1], b[bg][3]);
                }
        }

        if (c == 0) {
            if (lane == 0) MBAR_ARRIVE(sb + MB_EMPTY0);
            if (tid == 0) {
                MBAR_WAIT(sb + MB_EMPTY0, 0u);
                MBAR_EXPECT_TX(sb + MB_FULL0, (uint32_t)STAGE_BYTES);
                BULK_G2S(stA, gA + 3 * KBLK_BYTES, KBLK_BYTES, sb + MB_FULL0);
                BULK_G2S(stB, gB + 3 * KBLK_BYTES, KBLK_BYTES, sb + MB_FULL0);
            }
        }
    }

    // ---- epilogue: exp2(d * 0.5*log2 e) -> reduce; uniform tile-type branch ----
    const int rbase = warp_m * 32 + (lane >> 2);
    const int cbase = warp_n * 64 + 2 * (lane & 3);
    float sum = 0.0f;
    float sumd = 0.0f;

    if (!maskt && !bdiag) {
        #pragma unroll
        for (int am = 0; am < 2; am++)
            #pragma unroll
            for (int bn = 0; bn < 8; bn++)
                #pragma unroll
                for (int k = 0; k < 4; k++)
                    sum += ex2f(d[am][bn][k] * EXP_HALF_LOG2E);
    } else if (maskt) {
        #pragma unroll
        for (int am = 0; am < 2; am++)
            #pragma unroll
            for (int bn = 0; bn < 8; bn++)
                #pragma unroll
                for (int k = 0; k < 4; k++) {
                    float e = ex2f(d[am][bn][k] * EXP_HALF_LOG2E);
                    int row = rbase + am * 16 + ((k >> 1) << 3);
                    int col = cbase + bn * 8 + (k & 1);
                    sum += (col >= row) ? e : 0.0f;
                }
    } else {  // bdiag: full sum + harvest diagonal into sim_s
        #pragma unroll
        for (int am = 0; am < 2; am++)
            #pragma unroll
            for (int bn = 0; bn < 8; bn++)
                #pragma unroll
                for (int k = 0; k < 4; k++) {
                    float e = ex2f(d[am][bn][k] * EXP_HALF_LOG2E);
                    int row = rbase + am * 16 + ((k >> 1) << 3);
                    int col = cbase + bn * 8 + (k & 1);
                    sum += e;
                    if (row == col) sumd += e;
                }
    }

    #pragma unroll
    for (int o = 16; o > 0; o >>= 1)
        sum += __shfl_xor_sync(0xFFFFFFFFu, sum, o);

    __shared__ float wsum[8];
    if (lane == 0) wsum[wid] = sum;

    if (bdiag) {
        #pragma unroll
        for (int o = 16; o > 0; o >>= 1)
            sumd += __shfl_xor_sync(0xFFFFFFFFu, sumd, o);
        __shared__ float wsumd[8];
        if (lane == 0) wsumd[wid] = sumd;
        __syncthreads();
        if (tid == 0) {
            float s = 0.0f, sd = 0.0f;
            #pragma unroll
            for (int i = 0; i < 8; i++) { s += wsum[i]; sd += wsumd[i]; }
            atomicAdd(&g_main, (double)s);
            atomicAdd(&g_sims, (double)sd);
        }
    } else {
        __syncthreads();
        if (tid == 0) {
            float s = 0.0f;
            #pragma unroll
            for (int i = 0; i < 8; i++) s += wsum[i];
            atomicAdd(&g_main, (double)s);
        }
    }

    // ---- finalizer: last CTA computes the loss (fp32 only; cold branch) ----
    if (tid == 0) {
        __threadfence();
        int prev = atomicAdd(&g_done, 1);
        if (prev == NTILES - 1) {
            float mn   = (float)atomicAdd(&g_main, 0.0);   // coherent read
            float sims = (float)atomicAdd(&g_sims, 0.0);
            out[0] = lg2f((mn + sims) / sims) * LN2F;
            g_done = 0;                                    // replay-safe reset
            __threadfence();
        }
    }
}

// ---------------------------------------------------------------------------
extern "C" void kernel_launch(void* const* d_in, const int* in_sizes, int n_in,
                              void* d_out, int out_size) {
    const float* x = (const float*)d_in[0];
    float* out = (float*)d_out;

    cudaFuncSetAttribute(tile_k, cudaFuncAttributeMaxDynamicSharedMemorySize, SMEM_TOTAL);

    normalize_k<<<NROWS / 16, 256>>>(x);
    tile_k<<<NTILES, 256, SMEM_TOTAL>>>(out);
}